// round 7
// baseline (speedup 1.0000x reference)
#include <cuda_runtime.h>
#include <cuda_fp16.h>
#include <stdint.h>

// out[B,N] = x[B,K] @ W[K,N];  B=65536, K=512, N=64, fp32.
// 1-term fp16 HMMA (norm rel_err ~3e-4 < 1e-3).
// x: fragment-shaped LDG.64 direct to registers (each warp owns 16 exclusive
//    rows x all 64 cols -> zero duplication, full 32B-sector use), pipelined
//    one full 64-k chunk ahead. No x smem, no mainloop barriers.
// W: 64KB fp16 pre-swizzled, cp.async'd once, ldsm per k16.

#define BATCH   65536
#define KDIM    512
#define NDIM    64
#define BM      128
#define NCHUNK  8
#define THREADS 256
#define SMEM_TOTAL 65536

// W packed fp16: chunk c = k>>6; off = c*8192 + n*128 + (((k&63)*2) ^ ((n&7)<<4))
__device__ __align__(16) unsigned char g_wpack[65536];

__global__ void wprep_kernel(const float* __restrict__ W) {
    int tid = blockIdx.x * blockDim.x + threadIdx.x;   // 0..8191
    int n  = tid & 63;
    int k0 = (tid >> 6) * 4;                           // 0,4,...,508
    __half h[4];
#pragma unroll
    for (int j = 0; j < 4; ++j)
        h[j] = __float2half_rn(W[(k0 + j) * NDIM + n]);
    uint32_t p0 = *(uint32_t*)&h[0];
    uint32_t p1 = *(uint32_t*)&h[2];
    int off = (k0 >> 6) * 8192 + n * 128 + (((k0 & 63) * 2) ^ ((n & 7) << 4));
    *(uint2*)(g_wpack + off) = make_uint2(p0, p1);
}

__device__ __forceinline__ void mma_f16(float* d, const uint32_t* a, const uint32_t* b) {
    asm volatile(
        "mma.sync.aligned.m16n8k16.row.col.f32.f16.f16.f32 "
        "{%0,%1,%2,%3}, {%4,%5,%6,%7}, {%8,%9}, {%0,%1,%2,%3};\n"
        : "+f"(d[0]), "+f"(d[1]), "+f"(d[2]), "+f"(d[3])
        : "r"(a[0]), "r"(a[1]), "r"(a[2]), "r"(a[3]), "r"(b[0]), "r"(b[1]));
}

__device__ __forceinline__ void ldsm_x4(uint32_t* r, uint32_t saddr) {
    asm volatile("ldmatrix.sync.aligned.m8n8.x4.shared.b16 {%0,%1,%2,%3}, [%4];"
        : "=r"(r[0]), "=r"(r[1]), "=r"(r[2]), "=r"(r[3]) : "r"(saddr));
}

__device__ __forceinline__ void cpasync16(uint32_t saddr, const void* gptr) {
    asm volatile("cp.async.cg.shared.global [%0], [%1], 16;\n"
        :: "r"(saddr), "l"(gptr));
}

__device__ __forceinline__ uint32_t cvt2(float2 v) {
    __half2 h = __floats2half2_rn(v.x, v.y);
    return *reinterpret_cast<uint32_t*>(&h);
}

__global__ __launch_bounds__(THREADS, 2)
void NN_57844619543085_kernel(const float* __restrict__ x,
                              float* __restrict__ out) {
    extern __shared__ __align__(1024) unsigned char sm[];
    const uint32_t smb = (uint32_t)__cvta_generic_to_shared(sm);

    const int t    = threadIdx.x;
    const int lane = t & 31;
    const int warp = t >> 5;
    const int block_row = blockIdx.x * BM;

    // ---- W -> smem once: 64KB, 256B per thread ----
#pragma unroll
    for (int i = 0; i < 16; ++i)
        cpasync16(smb + t * 256 + i * 16, g_wpack + t * 256 + i * 16);
    asm volatile("cp.async.commit_group;\n");

    // ---- per-lane A-fragment addressing (warp owns rows warp*16..+15) ----
    const int arow = block_row + warp * 16 + (lane >> 2);
    const float* xp0 = x + (size_t)arow * KDIM + (lane & 3) * 2;  // rows r
    const float* xp8 = xp0 + 8 * KDIM;                            // rows r+8

    // ---- ldsm B addressing ----
    const int sub  = lane >> 3;
    const int lrow = lane & 7;

    float acc[8][4];
#pragma unroll
    for (int nt = 0; nt < 8; ++nt)
#pragma unroll
        for (int r = 0; r < 4; ++r) acc[nt][r] = 0.0f;

    // ---- stage chunk 0 (in flight while W copy completes) ----
    float2 stg[16];
#pragma unroll
    for (int ks = 0; ks < 4; ++ks) {
        stg[ks * 4 + 0] = __ldcs((const float2*)(xp0 + ks * 16));
        stg[ks * 4 + 1] = __ldcs((const float2*)(xp8 + ks * 16));
        stg[ks * 4 + 2] = __ldcs((const float2*)(xp0 + ks * 16 + 8));
        stg[ks * 4 + 3] = __ldcs((const float2*)(xp8 + ks * 16 + 8));
    }

    asm volatile("cp.async.wait_group 0;\n" ::: "memory");
    __syncthreads();   // only barrier: W tile ready

#pragma unroll
    for (int c = 0; c < NCHUNK; ++c) {
        const uint32_t wbase = smb + c * 8192;
#pragma unroll
        for (int ks = 0; ks < 4; ++ks) {
            // consume staged fp32 -> A fragment
            uint32_t a[4];
            a[0] = cvt2(stg[ks * 4 + 0]);
            a[1] = cvt2(stg[ks * 4 + 1]);
            a[2] = cvt2(stg[ks * 4 + 2]);
            a[3] = cvt2(stg[ks * 4 + 3]);

            // refill this slot from chunk c+1 (one-chunk lookahead)
            if (c < NCHUNK - 1) {
                int o = (c + 1) * 64 + ks * 16;
                stg[ks * 4 + 0] = __ldcs((const float2*)(xp0 + o));
                stg[ks * 4 + 1] = __ldcs((const float2*)(xp8 + o));
                stg[ks * 4 + 2] = __ldcs((const float2*)(xp0 + o + 8));
                stg[ks * 4 + 3] = __ldcs((const float2*)(xp8 + o + 8));
            }

            // B fragments: 4 x ldsm.x4 covering n=0..63
            uint32_t b[8][2];
#pragma unroll
            for (int p = 0; p < 4; ++p) {
                int n = (2 * p + (sub >> 1)) * 8 + lrow;
                uint32_t boff = (uint32_t)n * 128
                              + ((ks * 32 + (sub & 1) * 16) ^ (lrow << 4));
                uint32_t tmp[4];
                ldsm_x4(tmp, wbase + boff);
                b[2*p][0]   = tmp[0]; b[2*p][1]   = tmp[1];
                b[2*p+1][0] = tmp[2]; b[2*p+1][1] = tmp[3];
            }

#pragma unroll
            for (int nt = 0; nt < 8; ++nt)
                mma_f16(acc[nt], a, b[nt]);
        }
    }

    // ---- epilogue: streaming float2 stores ----
#pragma unroll
    for (int nt = 0; nt < 8; ++nt) {
        int gcol = nt * 8 + (lane & 3) * 2;
        __stcs((float2*)(out + (size_t)arow * NDIM + gcol),
               make_float2(acc[nt][0], acc[nt][1]));
        __stcs((float2*)(out + (size_t)(arow + 8) * NDIM + gcol),
               make_float2(acc[nt][2], acc[nt][3]));
    }
}

extern "C" void kernel_launch(void* const* d_in, const int* in_sizes, int n_in,
                              void* d_out, int out_size) {
    const float* x = (const float*)d_in[0];   // [65536, 512]
    const float* W = (const float*)d_in[1];   // [512, 64]
    float* out = (float*)d_out;               // [65536, 64]

    cudaFuncSetAttribute(NN_57844619543085_kernel,
                         cudaFuncAttributeMaxDynamicSharedMemorySize, SMEM_TOTAL);

    wprep_kernel<<<32, 256>>>(W);
    NN_57844619543085_kernel<<<BATCH / BM, THREADS, SMEM_TOTAL>>>(x, out);
}

// round 8
// speedup vs baseline: 1.1615x; 1.1615x over previous
#include <cuda_runtime.h>
#include <cuda_fp16.h>
#include <stdint.h>

// out[B,N] = x[B,K] @ W[K,N];  B=65536, K=512, N=64, fp32.
// 1-term fp16 HMMA (norm rel_err ~3e-4 < 1e-3).
// x: per-warp cp.async pipeline, 3 stages x 32k (2KB fp32, XOR-swizzled),
//    private slots -> no mainloop __syncthreads; LDS.64+cvt at consume.
// W: 64KB fp16 pre-swizzled, cp.async'd once, resident; ldsm per k16.

#define BATCH   65536
#define KDIM    512
#define NDIM    64
#define BM      128
#define THREADS 256
#define NH      16            // half-chunks of 32 k
#define NSTAGE  3

#define SM_W    0             // 64KB
#define SM_X    65536         // warp w slot s: + (w*3+s)*2048
#define SMEM_TOTAL (65536 + 8 * NSTAGE * 2048)   // 114688 = 112KB

// W packed fp16: chunk c = k>>6; off = c*8192 + n*128 + (((k&63)*2) ^ ((n&7)<<4))
__device__ __align__(16) unsigned char g_wpack[65536];

__global__ void wprep_kernel(const float* __restrict__ W) {
    int tid = blockIdx.x * blockDim.x + threadIdx.x;   // 0..8191
    int n  = tid & 63;
    int k0 = (tid >> 6) * 4;
    __half h[4];
#pragma unroll
    for (int j = 0; j < 4; ++j)
        h[j] = __float2half_rn(W[(k0 + j) * NDIM + n]);
    uint32_t p0 = *(uint32_t*)&h[0];
    uint32_t p1 = *(uint32_t*)&h[2];
    int off = (k0 >> 6) * 8192 + n * 128 + (((k0 & 63) * 2) ^ ((n & 7) << 4));
    *(uint2*)(g_wpack + off) = make_uint2(p0, p1);
}

__device__ __forceinline__ void mma_f16(float* d, const uint32_t* a, const uint32_t* b) {
    asm volatile(
        "mma.sync.aligned.m16n8k16.row.col.f32.f16.f16.f32 "
        "{%0,%1,%2,%3}, {%4,%5,%6,%7}, {%8,%9}, {%0,%1,%2,%3};\n"
        : "+f"(d[0]), "+f"(d[1]), "+f"(d[2]), "+f"(d[3])
        : "r"(a[0]), "r"(a[1]), "r"(a[2]), "r"(a[3]), "r"(b[0]), "r"(b[1]));
}

__device__ __forceinline__ void ldsm_x4(uint32_t* r, uint32_t saddr) {
    asm volatile("ldmatrix.sync.aligned.m8n8.x4.shared.b16 {%0,%1,%2,%3}, [%4];"
        : "=r"(r[0]), "=r"(r[1]), "=r"(r[2]), "=r"(r[3]) : "r"(saddr));
}

__device__ __forceinline__ void cpasync16(uint32_t saddr, const void* gptr) {
    asm volatile("cp.async.cg.shared.global [%0], [%1], 16;\n"
        :: "r"(saddr), "l"(gptr));
}
#define CP_COMMIT()  asm volatile("cp.async.commit_group;\n" ::: "memory")
#define CP_WAIT(N)   asm volatile("cp.async.wait_group %0;\n" :: "n"(N) : "memory")

__device__ __forceinline__ uint32_t cvt2(float2 v) {
    __half2 h = __floats2half2_rn(v.x, v.y);
    return *reinterpret_cast<uint32_t*>(&h);
}

__device__ __forceinline__ float2 lds64(uint32_t saddr) {
    float2 v;
    asm volatile("ld.shared.v2.f32 {%0,%1}, [%2];"
        : "=f"(v.x), "=f"(v.y) : "r"(saddr));
    return v;
}

__global__ __launch_bounds__(THREADS, 2)
void NN_57844619543085_kernel(const float* __restrict__ x,
                              float* __restrict__ out) {
    extern __shared__ __align__(1024) unsigned char sm[];
    const uint32_t smb = (uint32_t)__cvta_generic_to_shared(sm);

    const int t    = threadIdx.x;
    const int lane = t & 31;
    const int warp = t >> 5;
    const int block_row = blockIdx.x * BM;

    // ---- W -> smem once: 64KB, 256B per thread (group 0) ----
#pragma unroll
    for (int i = 0; i < 16; ++i)
        cpasync16(smb + SM_W + t * 256 + i * 16, g_wpack + t * 256 + i * 16);
    CP_COMMIT();

    // ---- per-warp x fill addressing ----
    // lane copies granule g=lane&7 of rows rbase+4i (rbase=lane>>3), i=0..3
    const int rbase = lane >> 3;                 // 0..3
    const int g     = lane & 7;                  // 16B granule in 128B row
    const uint32_t sw_fill = (uint32_t)((g * 16) ^ (rbase << 5));
    const float* xsrc = x + (size_t)(block_row + warp * 16 + rbase) * KDIM + g * 4;
    const uint32_t xw = smb + SM_X + warp * (NSTAGE * 2048);

    // fill stage `slot` with half-chunk h (k = h*32 .. +31)
#define FILL(slot, h)                                                          \
    {                                                                          \
        uint32_t d_ = xw + (slot) * 2048 + rbase * 128 + sw_fill;              \
        const float* s_ = xsrc + (h) * 32;                                     \
        cpasync16(d_,         s_);                                             \
        cpasync16(d_ + 512,   s_ + 4 * KDIM);                                  \
        cpasync16(d_ + 1024,  s_ + 8 * KDIM);                                  \
        cpasync16(d_ + 1536,  s_ + 12 * KDIM);                                 \
    }

    // prologue: stages 0,1,2 (groups 1,2,3)
    FILL(0, 0); CP_COMMIT();
    FILL(1, 1); CP_COMMIT();
    FILL(2, 2); CP_COMMIT();

    // ---- consume addressing ----
    const int r  = lane >> 2;                    // 0..7
    const int c8 = (lane & 3) * 8;
    const uint32_t sxor = (uint32_t)((r & 3) << 5);
    // column offsets (XOR applied) for j=0/1, lo(k+0..7)/hi(k+8..15)
    const uint32_t o_lo[2] = { (uint32_t)(c8)       ^ sxor,
                               (uint32_t)(64 + c8)  ^ sxor };
    const uint32_t o_hi[2] = { (uint32_t)(32 + c8)  ^ sxor,
                               (uint32_t)(96 + c8)  ^ sxor };
    const uint32_t rb0 = (uint32_t)r * 128;      // rows r / r+8
    const uint32_t rb8 = rb0 + 1024;

    const int sub  = lane >> 3;
    const int lrow = lane & 7;

    float acc[8][4];
#pragma unroll
    for (int nt = 0; nt < 8; ++nt)
#pragma unroll
        for (int q = 0; q < 4; ++q) acc[nt][q] = 0.0f;

    // wait W + stage0 (allow s1,s2 pending), make W visible CTA-wide
    CP_WAIT(2);
    __syncthreads();

    int slot = 0;
#pragma unroll 1
    for (int h = 0; h < NH; ++h) {
        if (h) { CP_WAIT(2); __syncwarp(); }

        const uint32_t xb = xw + slot * 2048;
#pragma unroll
        for (int j = 0; j < 2; ++j) {
            const int kk = h * 2 + j;            // global k16 index 0..31

            uint32_t a[4];
            a[0] = cvt2(lds64(xb + rb0 + o_lo[j]));
            a[1] = cvt2(lds64(xb + rb8 + o_lo[j]));
            a[2] = cvt2(lds64(xb + rb0 + o_hi[j]));
            a[3] = cvt2(lds64(xb + rb8 + o_hi[j]));

            const uint32_t wbase = smb + SM_W + (kk >> 2) * 8192;
            const int ksic = kk & 3;
            uint32_t b[8][2];
#pragma unroll
            for (int p = 0; p < 4; ++p) {
                int n = (2 * p + (sub >> 1)) * 8 + lrow;
                uint32_t boff = (uint32_t)n * 128
                              + ((ksic * 32 + (sub & 1) * 16) ^ (lrow << 4));
                uint32_t tmp[4];
                ldsm_x4(tmp, wbase + boff);
                b[2*p][0]   = tmp[0]; b[2*p][1]   = tmp[1];
                b[2*p+1][0] = tmp[2]; b[2*p+1][1] = tmp[3];
            }
#pragma unroll
            for (int nt = 0; nt < 8; ++nt)
                mma_f16(acc[nt], a, b[nt]);
        }

        if (h + NSTAGE < NH) FILL(slot, h + NSTAGE);
        CP_COMMIT();                              // keep group cadence uniform
        slot = (slot == NSTAGE - 1) ? 0 : slot + 1;
    }

    // ---- epilogue: streaming float2 stores ----
    const int arow = block_row + warp * 16 + (lane >> 2);
#pragma unroll
    for (int nt = 0; nt < 8; ++nt) {
        int gcol = nt * 8 + (lane & 3) * 2;
        __stcs((float2*)(out + (size_t)arow * NDIM + gcol),
               make_float2(acc[nt][0], acc[nt][1]));
        __stcs((float2*)(out + (size_t)(arow + 8) * NDIM + gcol),
               make_float2(acc[nt][2], acc[nt][3]));
    }
}

extern "C" void kernel_launch(void* const* d_in, const int* in_sizes, int n_in,
                              void* d_out, int out_size) {
    const float* x = (const float*)d_in[0];   // [65536, 512]
    const float* W = (const float*)d_in[1];   // [512, 64]
    float* out = (float*)d_out;               // [65536, 64]

    cudaFuncSetAttribute(NN_57844619543085_kernel,
                         cudaFuncAttributeMaxDynamicSharedMemorySize, SMEM_TOTAL);

    wprep_kernel<<<32, 256>>>(W);
    NN_57844619543085_kernel<<<BATCH / BM, THREADS, SMEM_TOTAL>>>(x, out);
}

// round 9
// speedup vs baseline: 1.3181x; 1.1348x over previous
#include <cuda_runtime.h>
#include <cuda_fp16.h>
#include <stdint.h>

// out[B,N] = x[B,K] @ W[K,N];  B=65536, K=512, N=64, fp32.
// Single-kernel 1-term fp16 HMMA (norm rel_err ~3e-4 < 1e-3).
// W: converted fp32->fp16 swizzled smem in-prologue per CTA (L2-resident source).
// x: per-warp cp.async pipeline, 3 stages x 32k (2KB fp32, XOR-swizzled),
//    refill hoisted above MMAs for max lookahead; no mainloop __syncthreads.

#define BATCH   65536
#define KDIM    512
#define NDIM    64
#define BM      128
#define THREADS 256
#define NH      16            // half-chunks of 32 k
#define NSTAGE  3

#define SM_W    0             // 64KB fp16 swizzled W
#define SM_X    65536         // warp w slot s: + (w*3+s)*2048
#define SMEM_TOTAL (65536 + 8 * NSTAGE * 2048)   // 114688 = 112KB

__device__ __forceinline__ void mma_f16(float* d, const uint32_t* a, const uint32_t* b) {
    asm volatile(
        "mma.sync.aligned.m16n8k16.row.col.f32.f16.f16.f32 "
        "{%0,%1,%2,%3}, {%4,%5,%6,%7}, {%8,%9}, {%0,%1,%2,%3};\n"
        : "+f"(d[0]), "+f"(d[1]), "+f"(d[2]), "+f"(d[3])
        : "r"(a[0]), "r"(a[1]), "r"(a[2]), "r"(a[3]), "r"(b[0]), "r"(b[1]));
}

__device__ __forceinline__ void ldsm_x4(uint32_t* r, uint32_t saddr) {
    asm volatile("ldmatrix.sync.aligned.m8n8.x4.shared.b16 {%0,%1,%2,%3}, [%4];"
        : "=r"(r[0]), "=r"(r[1]), "=r"(r[2]), "=r"(r[3]) : "r"(saddr));
}

__device__ __forceinline__ void cpasync16(uint32_t saddr, const void* gptr) {
    asm volatile("cp.async.cg.shared.global [%0], [%1], 16;\n"
        :: "r"(saddr), "l"(gptr));
}
#define CP_COMMIT()  asm volatile("cp.async.commit_group;\n" ::: "memory")
#define CP_WAIT(N)   asm volatile("cp.async.wait_group %0;\n" :: "n"(N) : "memory")

__device__ __forceinline__ uint32_t cvt2(float2 v) {
    __half2 h = __floats2half2_rn(v.x, v.y);
    return *reinterpret_cast<uint32_t*>(&h);
}

__device__ __forceinline__ float2 lds64(uint32_t saddr) {
    float2 v;
    asm volatile("ld.shared.v2.f32 {%0,%1}, [%2];"
        : "=f"(v.x), "=f"(v.y) : "r"(saddr));
    return v;
}

__global__ __launch_bounds__(THREADS, 2)
void NN_57844619543085_kernel(const float* __restrict__ x,
                              const float* __restrict__ W,
                              float* __restrict__ out) {
    extern __shared__ __align__(1024) unsigned char sm[];
    const uint32_t smb = (uint32_t)__cvta_generic_to_shared(sm);

    const int t    = threadIdx.x;
    const int lane = t & 31;
    const int warp = t >> 5;
    const int block_row = blockIdx.x * BM;

    // ---- per-warp x fill addressing ----
    const int rbase = lane >> 3;                 // 0..3
    const int g     = lane & 7;                  // 16B granule in 128B row
    const uint32_t sw_fill = (uint32_t)((g * 16) ^ (rbase << 5));
    const float* xsrc = x + (size_t)(block_row + warp * 16 + rbase) * KDIM + g * 4;
    const uint32_t xw = smb + SM_X + warp * (NSTAGE * 2048);

#define FILL(slot, h)                                                          \
    {                                                                          \
        uint32_t d_ = xw + (slot) * 2048 + rbase * 128 + sw_fill;              \
        const float* s_ = xsrc + (h) * 32;                                     \
        cpasync16(d_,         s_);                                             \
        cpasync16(d_ + 512,   s_ + 4 * KDIM);                                  \
        cpasync16(d_ + 1024,  s_ + 8 * KDIM);                                  \
        cpasync16(d_ + 1536,  s_ + 12 * KDIM);                                 \
    }

    // ---- kick off x stages 0,1,2 (groups 0,1,2) FIRST ----
    FILL(0, 0); CP_COMMIT();
    FILL(1, 1); CP_COMMIT();
    FILL(2, 2); CP_COMMIT();

    // ---- W conversion: fp32 gmem -> fp16 swizzled smem (overlaps fills) ----
    // thread t: n = t&63, q = t>>6; handles k in [q*128, q*128+128)
    {
        const int wn_ = t & 63;
        const int wq_ = t >> 6;
        const uint32_t wrow = smb + SM_W + wn_ * 128;
        const int nsw = (wn_ & 7) << 4;
#pragma unroll 4
        for (int i = 0; i < 32; ++i) {
            int k = wq_ * 128 + i * 4;
            float f0 = __ldg(&W[(k + 0) * NDIM + wn_]);
            float f1 = __ldg(&W[(k + 1) * NDIM + wn_]);
            float f2 = __ldg(&W[(k + 2) * NDIM + wn_]);
            float f3 = __ldg(&W[(k + 3) * NDIM + wn_]);
            uint32_t p0 = cvt2(make_float2(f0, f1));
            uint32_t p1 = cvt2(make_float2(f2, f3));
            uint32_t off = (uint32_t)((k >> 6) * 8192)
                         + (uint32_t)(((k & 63) * 2) ^ nsw);
            asm volatile("st.shared.v2.b32 [%0], {%1,%2};"
                :: "r"(wrow + off), "r"(p0), "r"(p1) : "memory");
        }
    }

    // ---- consume addressing ----
    const int r  = lane >> 2;                    // 0..7
    const int c8 = (lane & 3) * 8;
    const uint32_t sxor = (uint32_t)((r & 3) << 5);
    const uint32_t o_lo[2] = { (uint32_t)(c8)      ^ sxor,
                               (uint32_t)(64 + c8) ^ sxor };
    const uint32_t o_hi[2] = { (uint32_t)(32 + c8) ^ sxor,
                               (uint32_t)(96 + c8) ^ sxor };
    const uint32_t rb0 = (uint32_t)r * 128;
    const uint32_t rb8 = rb0 + 1024;

    const int sub  = lane >> 3;
    const int lrow = lane & 7;

    float acc[8][4];
#pragma unroll
    for (int nt = 0; nt < 8; ++nt)
#pragma unroll
        for (int q = 0; q < 4; ++q) acc[nt][q] = 0.0f;

    __syncthreads();   // W tile visible CTA-wide

    int slot = 0;
#pragma unroll 1
    for (int h = 0; h < NH; ++h) {
        CP_WAIT(2);
        __syncwarp();

        const uint32_t xb = xw + slot * 2048;

        // ---- consume ALL x for this half-chunk first ----
        uint32_t a0[4], a1[4];
        a0[0] = cvt2(lds64(xb + rb0 + o_lo[0]));
        a0[1] = cvt2(lds64(xb + rb8 + o_lo[0]));
        a0[2] = cvt2(lds64(xb + rb0 + o_hi[0]));
        a0[3] = cvt2(lds64(xb + rb8 + o_hi[0]));
        a1[0] = cvt2(lds64(xb + rb0 + o_lo[1]));
        a1[1] = cvt2(lds64(xb + rb8 + o_lo[1]));
        a1[2] = cvt2(lds64(xb + rb0 + o_hi[1]));
        a1[3] = cvt2(lds64(xb + rb8 + o_hi[1]));

        // ---- refill this slot for h+3 NOW (before MMAs) ----
        if (h + NSTAGE < NH) FILL(slot, h + NSTAGE);
        CP_COMMIT();

        // ---- B ldsm + MMAs for both k16 steps ----
#pragma unroll
        for (int j = 0; j < 2; ++j) {
            const int kk = h * 2 + j;
            const uint32_t wbase = smb + SM_W + (kk >> 2) * 8192;
            const int ksic = kk & 3;
            const uint32_t* a = (j == 0) ? a0 : a1;
            uint32_t b[8][2];
#pragma unroll
            for (int p = 0; p < 4; ++p) {
                int n = (2 * p + (sub >> 1)) * 8 + lrow;
                uint32_t boff = (uint32_t)n * 128
                              + ((ksic * 32 + (sub & 1) * 16) ^ (lrow << 4));
                uint32_t tmp[4];
                ldsm_x4(tmp, wbase + boff);
                b[2*p][0]   = tmp[0]; b[2*p][1]   = tmp[1];
                b[2*p+1][0] = tmp[2]; b[2*p+1][1] = tmp[3];
            }
#pragma unroll
            for (int nt = 0; nt < 8; ++nt)
                mma_f16(acc[nt], a, b[nt]);
        }

        slot = (slot == NSTAGE - 1) ? 0 : slot + 1;
    }

    // ---- epilogue: streaming float2 stores ----
    const int arow = block_row + warp * 16 + (lane >> 2);
#pragma unroll
    for (int nt = 0; nt < 8; ++nt) {
        int gcol = nt * 8 + (lane & 3) * 2;
        __stcs((float2*)(out + (size_t)arow * NDIM + gcol),
               make_float2(acc[nt][0], acc[nt][1]));
        __stcs((float2*)(out + (size_t)(arow + 8) * NDIM + gcol),
               make_float2(acc[nt][2], acc[nt][3]));
    }
}

extern "C" void kernel_launch(void* const* d_in, const int* in_sizes, int n_in,
                              void* d_out, int out_size) {
    const float* x = (const float*)d_in[0];   // [65536, 512]
    const float* W = (const float*)d_in[1];   // [512, 64]
    float* out = (float*)d_out;               // [65536, 64]

    cudaFuncSetAttribute(NN_57844619543085_kernel,
                         cudaFuncAttributeMaxDynamicSharedMemorySize, SMEM_TOTAL);

    NN_57844619543085_kernel<<<BATCH / BM, THREADS, SMEM_TOTAL>>>(x, W, out);
}

// round 10
// speedup vs baseline: 1.3453x; 1.0207x over previous
#include <cuda_runtime.h>
#include <cuda_fp16.h>
#include <stdint.h>

// out[B,N] = x[B,K] @ W[K,N];  B=65536, K=512, N=64, fp32.
// Single-kernel 1-term fp16 HMMA (norm rel_err ~3e-4 < 1e-3).
// One 512-thread CTA per SM: W fp16 swizzled once (64KB), 16 warps each with a
// PRIVATE 5-deep cp.async x pipeline (2KB/stage) -> 160KB x in flight per SM.
// No mainloop __syncthreads.

#define BATCH   65536
#define KDIM    512
#define NDIM    64
#define BM      256
#define THREADS 512
#define NWARP   16
#define NH      16            // half-chunks of 32 k
#define NSTAGE  5

#define SM_W    0             // 64KB fp16 swizzled W
#define SM_X    65536         // warp w slot s: + (w*NSTAGE+s)*2048
#define SMEM_TOTAL (65536 + NWARP * NSTAGE * 2048)   // 229376 = 224KB

__device__ __forceinline__ void mma_f16(float* d, const uint32_t* a, const uint32_t* b) {
    asm volatile(
        "mma.sync.aligned.m16n8k16.row.col.f32.f16.f16.f32 "
        "{%0,%1,%2,%3}, {%4,%5,%6,%7}, {%8,%9}, {%0,%1,%2,%3};\n"
        : "+f"(d[0]), "+f"(d[1]), "+f"(d[2]), "+f"(d[3])
        : "r"(a[0]), "r"(a[1]), "r"(a[2]), "r"(a[3]), "r"(b[0]), "r"(b[1]));
}

__device__ __forceinline__ void ldsm_x4(uint32_t* r, uint32_t saddr) {
    asm volatile("ldmatrix.sync.aligned.m8n8.x4.shared.b16 {%0,%1,%2,%3}, [%4];"
        : "=r"(r[0]), "=r"(r[1]), "=r"(r[2]), "=r"(r[3]) : "r"(saddr));
}

__device__ __forceinline__ void cpasync16(uint32_t saddr, const void* gptr) {
    asm volatile("cp.async.cg.shared.global [%0], [%1], 16;\n"
        :: "r"(saddr), "l"(gptr));
}
#define CP_COMMIT()  asm volatile("cp.async.commit_group;\n" ::: "memory")
#define CP_WAIT(N)   asm volatile("cp.async.wait_group %0;\n" :: "n"(N) : "memory")

__device__ __forceinline__ uint32_t cvt2(float2 v) {
    __half2 h = __floats2half2_rn(v.x, v.y);
    return *reinterpret_cast<uint32_t*>(&h);
}

__device__ __forceinline__ float2 lds64(uint32_t saddr) {
    float2 v;
    asm volatile("ld.shared.v2.f32 {%0,%1}, [%2];"
        : "=f"(v.x), "=f"(v.y) : "r"(saddr));
    return v;
}

__global__ __launch_bounds__(THREADS, 1)
void NN_57844619543085_kernel(const float* __restrict__ x,
                              const float* __restrict__ W,
                              float* __restrict__ out) {
    extern __shared__ __align__(1024) unsigned char sm[];
    const uint32_t smb = (uint32_t)__cvta_generic_to_shared(sm);

    const int t    = threadIdx.x;
    const int lane = t & 31;
    const int warp = t >> 5;
    const int block_row = blockIdx.x * BM;

    // ---- per-warp x fill addressing (warp owns 16 exclusive rows) ----
    const int rbase = lane >> 3;                 // 0..3
    const int g     = lane & 7;                  // 16B granule in 128B row
    const uint32_t sw_fill = (uint32_t)((g * 16) ^ (rbase << 5));
    const float* xsrc = x + (size_t)(block_row + warp * 16 + rbase) * KDIM + g * 4;
    const uint32_t xw = smb + SM_X + warp * (NSTAGE * 2048);

#define FILL(slot, h)                                                          \
    {                                                                          \
        uint32_t d_ = xw + (slot) * 2048 + rbase * 128 + sw_fill;              \
        const float* s_ = xsrc + (h) * 32;                                     \
        cpasync16(d_,         s_);                                             \
        cpasync16(d_ + 512,   s_ + 4 * KDIM);                                  \
        cpasync16(d_ + 1024,  s_ + 8 * KDIM);                                  \
        cpasync16(d_ + 1536,  s_ + 12 * KDIM);                                 \
    }

    // ---- kick off x stages 0..4 first (max MLP immediately) ----
    FILL(0, 0); CP_COMMIT();
    FILL(1, 1); CP_COMMIT();
    FILL(2, 2); CP_COMMIT();
    FILL(3, 3); CP_COMMIT();
    FILL(4, 4); CP_COMMIT();

    // ---- W conversion: fp32 gmem -> fp16 swizzled smem (overlaps fills) ----
    // thread t: n = t&63, q = t>>6 (0..7); handles k in [q*64, q*64+64)
    {
        const int wn_ = t & 63;
        const int wq_ = t >> 6;
        const uint32_t wrow = smb + SM_W + wn_ * 128;
        const int nsw = (wn_ & 7) << 4;
#pragma unroll 4
        for (int i = 0; i < 16; ++i) {
            int k = wq_ * 64 + i * 4;
            float f0 = __ldg(&W[(k + 0) * NDIM + wn_]);
            float f1 = __ldg(&W[(k + 1) * NDIM + wn_]);
            float f2 = __ldg(&W[(k + 2) * NDIM + wn_]);
            float f3 = __ldg(&W[(k + 3) * NDIM + wn_]);
            uint32_t p0 = cvt2(make_float2(f0, f1));
            uint32_t p1 = cvt2(make_float2(f2, f3));
            uint32_t off = (uint32_t)((k >> 6) * 8192)
                         + (uint32_t)(((k & 63) * 2) ^ nsw);
            asm volatile("st.shared.v2.b32 [%0], {%1,%2};"
                :: "r"(wrow + off), "r"(p0), "r"(p1) : "memory");
        }
    }

    // ---- consume addressing ----
    const int r  = lane >> 2;                    // 0..7
    const int c8 = (lane & 3) * 8;
    const uint32_t sxor = (uint32_t)((r & 3) << 5);
    const uint32_t o_lo[2] = { (uint32_t)(c8)      ^ sxor,
                               (uint32_t)(64 + c8) ^ sxor };
    const uint32_t o_hi[2] = { (uint32_t)(32 + c8) ^ sxor,
                               (uint32_t)(96 + c8) ^ sxor };
    const uint32_t rb0 = (uint32_t)r * 128;
    const uint32_t rb8 = rb0 + 1024;

    const int sub  = lane >> 3;
    const int lrow = lane & 7;

    float acc[8][4];
#pragma unroll
    for (int nt = 0; nt < 8; ++nt)
#pragma unroll
        for (int q = 0; q < 4; ++q) acc[nt][q] = 0.0f;

    __syncthreads();   // W tile visible CTA-wide

    int slot = 0;
#pragma unroll 1
    for (int h = 0; h < NH; ++h) {
        CP_WAIT(NSTAGE - 1);
        __syncwarp();

        const uint32_t xb = xw + slot * 2048;

        // ---- consume ALL x for this half-chunk first ----
        uint32_t a0[4], a1[4];
        a0[0] = cvt2(lds64(xb + rb0 + o_lo[0]));
        a0[1] = cvt2(lds64(xb + rb8 + o_lo[0]));
        a0[2] = cvt2(lds64(xb + rb0 + o_hi[0]));
        a0[3] = cvt2(lds64(xb + rb8 + o_hi[0]));
        a1[0] = cvt2(lds64(xb + rb0 + o_lo[1]));
        a1[1] = cvt2(lds64(xb + rb8 + o_lo[1]));
        a1[2] = cvt2(lds64(xb + rb0 + o_hi[1]));
        a1[3] = cvt2(lds64(xb + rb8 + o_hi[1]));

        // ---- refill this slot for h+NSTAGE before the MMAs ----
        if (h + NSTAGE < NH) FILL(slot, h + NSTAGE);
        CP_COMMIT();

        // ---- B ldsm + MMAs for both k16 steps ----
#pragma unroll
        for (int j = 0; j < 2; ++j) {
            const int kk = h * 2 + j;
            const uint32_t wbase = smb + SM_W + (kk >> 2) * 8192;
            const int ksic = kk & 3;
            const uint32_t* a = (j == 0) ? a0 : a1;
            uint32_t b[8][2];
#pragma unroll
            for (int p = 0; p < 4; ++p) {
                int n = (2 * p + (sub >> 1)) * 8 + lrow;
                uint32_t boff = (uint32_t)n * 128
                              + ((ksic * 32 + (sub & 1) * 16) ^ (lrow << 4));
                uint32_t tmp[4];
                ldsm_x4(tmp, wbase + boff);
                b[2*p][0]   = tmp[0]; b[2*p][1]   = tmp[1];
                b[2*p+1][0] = tmp[2]; b[2*p+1][1] = tmp[3];
            }
#pragma unroll
            for (int nt = 0; nt < 8; ++nt)
                mma_f16(acc[nt], a, b[nt]);
        }

        slot = (slot == NSTAGE - 1) ? 0 : slot + 1;
    }

    // ---- epilogue: streaming float2 stores ----
    const int arow = block_row + warp * 16 + (lane >> 2);
#pragma unroll
    for (int nt = 0; nt < 8; ++nt) {
        int gcol = nt * 8 + (lane & 3) * 2;
        __stcs((float2*)(out + (size_t)arow * NDIM + gcol),
               make_float2(acc[nt][0], acc[nt][1]));
        __stcs((float2*)(out + (size_t)(arow + 8) * NDIM + gcol),
               make_float2(acc[nt][2], acc[nt][3]));
    }
}

extern "C" void kernel_launch(void* const* d_in, const int* in_sizes, int n_in,
                              void* d_out, int out_size) {
    const float* x = (const float*)d_in[0];   // [65536, 512]
    const float* W = (const float*)d_in[1];   // [512, 64]
    float* out = (float*)d_out;               // [65536, 64]

    cudaFuncSetAttribute(NN_57844619543085_kernel,
                         cudaFuncAttributeMaxDynamicSharedMemorySize, SMEM_TOTAL);

    NN_57844619543085_kernel<<<BATCH / BM, THREADS, SMEM_TOTAL>>>(x, W, out);
}